// round 7
// baseline (speedup 1.0000x reference)
#include <cuda_runtime.h>
#include <cuda_bf16.h>
#include <cstdint>

#define NTOT 4096
#define FIN  128
#define FOUT 64
#define NH   4
#define NCOL 256           // NH*FOUT
#define NEG_INF -1.0e9f

// ---------------- scratch (device globals; no allocations) ----------------
__device__ float g_mask[(size_t)NTOT * NTOT];   // 64 MB
__device__ float g_P[NTOT * NCOL];              // proj, [n][h*64+o]
__device__ float g_S[NTOT * NCOL];              // skip, [n][c]
__device__ __nv_bfloat16 g_Bt[NH * FOUT * NTOT];// B^T bf16, [h][f][j]
__device__ float g_ssrc[NH * NTOT];
__device__ float g_stgt[NH * NTOT];
__device__ float g_cpart[32 * NH * NTOT];       // [rowtile][h][j]
__device__ float g_rpsum[32 * NTOT];            // [coltile][row]
__device__ float g_rpsq[32 * NTOT];
__device__ float g_mu[NTOT];
__device__ float g_rsig[NTOT];

// ---------------- helpers ----------------
__device__ __forceinline__ uint32_t smem_u32(const void* p) {
    uint32_t a;
    asm("{ .reg .u64 t; cvta.to.shared.u64 t, %1; cvt.u32.u64 %0, t; }" : "=r"(a) : "l"(p));
    return a;
}
#define SWZ(o) ((o) ^ (((o) >> 3) & 0x70))

__device__ __forceinline__ void ldm4(uint32_t* r, uint32_t addr) {
    asm volatile("ldmatrix.sync.aligned.m8n8.x4.shared.b16 {%0,%1,%2,%3}, [%4];"
                 : "=r"(r[0]), "=r"(r[1]), "=r"(r[2]), "=r"(r[3]) : "r"(addr));
}
__device__ __forceinline__ void mma16816(float* d, const uint32_t* a,
                                         uint32_t b0, uint32_t b1) {
    asm volatile("mma.sync.aligned.m16n8k16.row.col.f32.bf16.bf16.f32 "
                 "{%0,%1,%2,%3}, {%4,%5,%6,%7}, {%8,%9}, {%0,%1,%2,%3};"
                 : "+f"(d[0]), "+f"(d[1]), "+f"(d[2]), "+f"(d[3])
                 : "r"(a[0]), "r"(a[1]), "r"(a[2]), "r"(a[3]), "r"(b0), "r"(b1));
}

// ---------------- K1: X @ [proj | skip^T] -> g_P, g_S ----------------
__global__ __launch_bounds__(256) void k_gemm1(const float* __restrict__ X,
                                               const float* __restrict__ Wp,
                                               const float* __restrict__ Wsk) {
    __shared__ float As[32 * 132];
    __shared__ float Ws[32 * 68];
    const int tid = threadIdx.x;
    const int bx = blockIdx.x, by = blockIdx.y;
    const int i0 = bx * 128;
    const int tr = tid >> 4;
    const int tc = tid & 15;

    float acc[8][4];
#pragma unroll
    for (int u = 0; u < 8; u++)
#pragma unroll
        for (int v = 0; v < 4; v++) acc[u][v] = 0.f;

    for (int s = 0; s < 4; s++) {
        const int k0 = s * 32;
        __syncthreads();
        {
            const int rl = tid >> 3;
            const int kl = (tid & 7) << 2;
#pragma unroll
            for (int p = 0; p < 4; p++) {
                const int r = rl + p * 32;
                float4 v = *(const float4*)(X + (i0 + r) * FIN + k0 + kl);
                As[(kl + 0) * 132 + r] = v.x;
                As[(kl + 1) * 132 + r] = v.y;
                As[(kl + 2) * 132 + r] = v.z;
                As[(kl + 3) * 132 + r] = v.w;
            }
        }
        if (by < 4) {
            const int kq = tid >> 4;
            const int c4 = (tid & 15) << 2;
#pragma unroll
            for (int p = 0; p < 2; p++) {
                const int kk = kq + p * 16;
                float4 v = *(const float4*)(Wp + by * (FIN * FOUT) + (k0 + kk) * FOUT + c4);
                *(float4*)(Ws + kk * 68 + c4) = v;
            }
        } else {
            const int kl = tid & 31;
            const int cg = tid >> 5;
            const int cb = (by - 4) * 64;
#pragma unroll
            for (int p = 0; p < 8; p++) {
                const int cc = cg * 8 + p;
                Ws[kl * 68 + cc] = Wsk[(cb + cc) * FIN + k0 + kl];
            }
        }
        __syncthreads();
#pragma unroll
        for (int k = 0; k < 32; k++) {
            float4 a0 = *(const float4*)(As + k * 132 + tr * 8);
            float4 a1 = *(const float4*)(As + k * 132 + tr * 8 + 4);
            float4 b  = *(const float4*)(Ws + k * 68 + tc * 4);
            float av[8] = {a0.x, a0.y, a0.z, a0.w, a1.x, a1.y, a1.z, a1.w};
            float bv[4] = {b.x, b.y, b.z, b.w};
#pragma unroll
            for (int u = 0; u < 8; u++)
#pragma unroll
                for (int v = 0; v < 4; v++) acc[u][v] += av[u] * bv[v];
        }
    }
    float* dst = (by < 4) ? g_P : g_S;
    const int cglob = (by & 3) * 64 + tc * 4;
#pragma unroll
    for (int u = 0; u < 8; u++) {
        const int row = i0 + tr * 8 + u;
        *(float4*)(dst + row * NCOL + cglob) =
            make_float4(acc[u][0], acc[u][1], acc[u][2], acc[u][3]);
    }
}

// ---------------- K1b: per-(h,n) scalar scores ----------------
__global__ void k_scores(const float* __restrict__ Wsrc, const float* __restrict__ Wtgt) {
    const int p = blockIdx.x * blockDim.x + threadIdx.x;
    const int n = p >> 2, h = p & 3;
    const float4* pr = (const float4*)(g_P + n * NCOL + h * FOUT);
    const float4* ws = (const float4*)(Wsrc + h * FOUT);
    const float4* wt = (const float4*)(Wtgt + h * FOUT);
    float ss = 0.f, st = 0.f;
#pragma unroll
    for (int o = 0; o < 16; o++) {
        float4 pv = pr[o], a = ws[o], b = wt[o];
        ss += pv.x * a.x + pv.y * a.y + pv.z * a.z + pv.w * a.w;
        st += pv.x * b.x + pv.y * b.y + pv.z * b.z + pv.w * b.w;
    }
    g_ssrc[h * NTOT + n] = ss;
    g_stgt[h * NTOT + n] = st;
}

// ---------------- K2: mask + colsum partials + row-stat partials ----------------
__device__ __forceinline__ float mask_val(float d, float b, float cut) {
    const float wdm = d + b;
    return (wdm > 0.f) ? wdm : ((b > cut) ? (b + wdm) : NEG_INF);
}

__global__ __launch_bounds__(256) void k_mask(const float* __restrict__ deg,
                                              const float* __restrict__ bond,
                                              const int* __restrict__ cutp) {
    __shared__ float Ssr[NH][128];
    __shared__ float Stg[NH][128];
    __shared__ float red[8][NH][128];
    const int tid = threadIdx.x;
    const int bx = blockIdx.x, by = blockIdx.y;
    const int j0 = bx * 128, i0 = by * 128;
    const float cut = (float)cutp[0];

    for (int idx = tid; idx < NH * 128; idx += 256) {
        const int h = idx >> 7, q = idx & 127;
        Ssr[h][q] = g_ssrc[h * NTOT + i0 + q];
        Stg[h][q] = g_stgt[h * NTOT + j0 + q];
    }
    __syncthreads();

    const int w = tid >> 5, l = tid & 31;
    float cs[NH][4];
#pragma unroll
    for (int h = 0; h < NH; h++)
#pragma unroll
        for (int u = 0; u < 4; u++) cs[h][u] = 0.f;
    float tg[NH][4];
#pragma unroll
    for (int h = 0; h < NH; h++)
#pragma unroll
        for (int u = 0; u < 4; u++) tg[h][u] = Stg[h][l * 4 + u];

    for (int rr = 0; rr < 16; rr++) {
        const int row = i0 + w * 16 + rr;
        const size_t base = (size_t)row * NTOT + j0 + l * 4;
        float4 d = *(const float4*)(deg + base);
        float4 b = *(const float4*)(bond + base);
        float m[4];
        m[0] = mask_val(d.x, b.x, cut);
        m[1] = mask_val(d.y, b.y, cut);
        m[2] = mask_val(d.z, b.z, cut);
        m[3] = mask_val(d.w, b.w, cut);
        *(float4*)(g_mask + base) = make_float4(m[0], m[1], m[2], m[3]);

        float rs = m[0] + m[1] + m[2] + m[3];
        float rq = m[0] * m[0] + m[1] * m[1] + m[2] * m[2] + m[3] * m[3];
#pragma unroll
        for (int off = 16; off > 0; off >>= 1) {
            rs += __shfl_xor_sync(0xffffffffu, rs, off);
            rq += __shfl_xor_sync(0xffffffffu, rq, off);
        }
        if (l == 0) { g_rpsum[bx * NTOT + row] = rs; g_rpsq[bx * NTOT + row] = rq; }

#pragma unroll
        for (int h = 0; h < NH; h++) {
            const float a = Ssr[h][w * 16 + rr];
#pragma unroll
            for (int u = 0; u < 4; u++) {
                float v = a + tg[h][u];
                v = fmaxf(v, 0.2f * v);
                cs[h][u] += __expf(m[u] + v);
            }
        }
    }
#pragma unroll
    for (int h = 0; h < NH; h++)
#pragma unroll
        for (int u = 0; u < 4; u++) red[w][h][l * 4 + u] = cs[h][u];
    __syncthreads();
    for (int o = tid; o < NH * 128; o += 256) {
        const int h = o >> 7, jj = o & 127;
        float s = 0.f;
#pragma unroll
        for (int ww = 0; ww < 8; ww++) s += red[ww][h][jj];
        g_cpart[(by * NH + h) * NTOT + j0 + jj] = s;
    }
}

// ---------------- K2b: parallel partial reduce + bf16 B^T production ----------------
// grid 256, block 256; each block handles 16 j values.
__global__ __launch_bounds__(256) void k_finalize() {
    __shared__ float cinv_s[NH][16];
    __shared__ float red2[32];
    __shared__ float st[16][260];
    const int t = threadIdx.x;
    const int j0 = blockIdx.x * 16;

    // column sums: 64 (h,j) pairs, 4 threads each summing 8 partials
    {
        const int pair = t >> 2, sub = t & 3;
        const int hh = pair >> 4, jj = pair & 15;
        float c = 0.f;
#pragma unroll
        for (int p = 0; p < 8; p++)
            c += g_cpart[((sub * 8 + p) * NH + hh) * NTOT + j0 + jj];
        c += __shfl_xor_sync(0xffffffffu, c, 1);
        c += __shfl_xor_sync(0xffffffffu, c, 2);
        if (sub == 0) cinv_s[hh][jj] = 1.0f / c;
    }
    // row stats: t<128 -> rpsum, t>=128 -> rpsq; 8 threads per j, 4 partials each
    {
        const int j = (t >> 3) & 15, sub = t & 7;
        const float* src = (t < 128) ? g_rpsum : g_rpsq;
        float a = 0.f;
#pragma unroll
        for (int p = 0; p < 4; p++) a += src[(sub * 4 + p) * NTOT + j0 + j];
        a += __shfl_xor_sync(0xffffffffu, a, 1);
        a += __shfl_xor_sync(0xffffffffu, a, 2);
        a += __shfl_xor_sync(0xffffffffu, a, 4);
        if (sub == 0) red2[((t >> 7) << 4) + j] = a;
    }
    // stage g_P tile [16 rows x 256 cols]
    {
        const int jr = t >> 4, cg = (t & 15) * 16;
#pragma unroll
        for (int z = 0; z < 4; z++) {
            float4 v = *(const float4*)(g_P + (size_t)(j0 + jr) * NCOL + cg + z * 4);
            st[jr][cg + z * 4 + 0] = v.x;
            st[jr][cg + z * 4 + 1] = v.y;
            st[jr][cg + z * 4 + 2] = v.z;
            st[jr][cg + z * 4 + 3] = v.w;
        }
    }
    __syncthreads();
    if (t < 16) {
        const float mu = red2[t] * (1.0f / NTOT);
        const float var = red2[16 + t] * (1.0f / NTOT) - mu * mu;
        g_mu[j0 + t] = mu;
        g_rsig[j0 + t] = rsqrtf(fmaxf(var, 0.f) + 1e-5f);
    }
    // B^T: thread t -> h = t>>6, f = t&63, all 16 j
    {
        const int hh = t >> 6, f = t & 63;
        __nv_bfloat16 tmp[16];
#pragma unroll
        for (int z = 0; z < 16; z++)
            tmp[z] = __float2bfloat16(st[z][hh * 64 + f] * cinv_s[hh][z]);
        __nv_bfloat16* dst = g_Bt + ((size_t)hh * FOUT + f) * NTOT + j0;
        *(uint4*)(dst + 0) = *(uint4*)(tmp + 0);
        *(uint4*)(dst + 8) = *(uint4*)(tmp + 8);
    }
}

// ---------------- K3: HMMA GEMM, A-fragments generated in registers ----------------
// grid (32, 4): bx = 128-row tile, by = head. K staged by 64 j, B double buffered.
// 8 warps, warp tile M=16 x N=64 (no A sharing between warps -> exp direct to frags).
__global__ __launch_bounds__(256, 1) void k_attn(float* __restrict__ outY,
                                                 float* __restrict__ outLN) {
    __shared__ float tg_s[NTOT];
    __shared__ __align__(1024) char Bbuf[2][8192];
    const int tid = threadIdx.x;
    const int wid = tid >> 5;
    const int l = tid & 31;
    const int i0 = blockIdx.x * 128;
    const int h = blockIdx.y;

    const int row0l = wid * 16 + (l >> 2);    // local row (0..127)
    const int row1l = row0l + 8;
    const int q2 = (l & 3) * 2;
    const int bf = tid >> 2, bq = tid & 3;    // B staging map

    // preload target scores for this head
#pragma unroll
    for (int p = 0; p < 16; p++) tg_s[tid + p * 256] = g_stgt[h * NTOT + tid + p * 256];

    const float s0 = g_ssrc[h * NTOT + i0 + row0l];
    const float s1 = g_ssrc[h * NTOT + i0 + row1l];
    const float mu0 = g_mu[i0 + row0l], rg0 = g_rsig[i0 + row0l];
    const float mu1 = g_mu[i0 + row1l], rg1 = g_rsig[i0 + row1l];

    // ldmatrix offsets for B (all warps read full 64xN tile)
    const int quad = l >> 3, lr = l & 7;
    uint32_t offB[4][4];
#pragma unroll
    for (int nt = 0; nt < 4; nt++)
#pragma unroll
        for (int kc = 0; kc < 4; kc++)
            offB[nt][kc] = SWZ((nt * 16 + (quad & 1) * 8 + lr) * 128
                               + (kc * 16 + (quad >> 1) * 8) * 2);
    const uint32_t smbB = smem_u32(Bbuf);

    float acc[8][4];
#pragma unroll
    for (int nt = 0; nt < 8; nt++)
#pragma unroll
        for (int z = 0; z < 4; z++) acc[nt][z] = 0.f;

    // prefetch stage 0
    float2 mvA[8], mvB[8];
    uint4 bv0, bv1;
#pragma unroll
    for (int kc = 0; kc < 4; kc++)
#pragma unroll
        for (int hf = 0; hf < 2; hf++) {
            const int c = kc * 16 + hf * 8 + q2;
            mvA[kc * 2 + hf] = *(const float2*)(g_mask + (size_t)(i0 + row0l) * NTOT + c);
            mvB[kc * 2 + hf] = *(const float2*)(g_mask + (size_t)(i0 + row1l) * NTOT + c);
        }
    {
        const __nv_bfloat16* src = g_Bt + ((size_t)h * FOUT + bf) * NTOT + bq * 16;
        bv0 = *(const uint4*)(src);
        bv1 = *(const uint4*)(src + 8);
    }
    __syncthreads();   // tg_s ready

    for (int kt = 0; kt < 64; kt++) {
        const int b = kt & 1;
        const int j0 = kt * 64;
        char* Bb = Bbuf[b];

        // stage B tile into smem (double buffered; one sync per stage is safe)
        *(uint4*)(Bb + SWZ(bf * 128 + bq * 32)) = bv0;
        *(uint4*)(Bb + SWZ(bf * 128 + bq * 32 + 16)) = bv1;
        __syncthreads();

        // ---- exp -> A fragments (registers), fused LN quarter ----
        const bool do_ln = ((kt >> 4) == h);
        uint32_t areg[4][4];
#pragma unroll
        for (int kc = 0; kc < 4; kc++) {
#pragma unroll
            for (int hf = 0; hf < 2; hf++) {
                const int c = j0 + kc * 16 + hf * 8 + q2;
                const float2 tg = *(const float2*)(tg_s + c);
                const float2 ma = mvA[kc * 2 + hf];
                const float2 mb = mvB[kc * 2 + hf];
                if (do_ln) {
                    *(float2*)(outLN + (size_t)(i0 + row0l) * NTOT + c) =
                        make_float2((ma.x - mu0) * rg0, (ma.y - mu0) * rg0);
                    *(float2*)(outLN + (size_t)(i0 + row1l) * NTOT + c) =
                        make_float2((mb.x - mu1) * rg1, (mb.y - mu1) * rg1);
                }
                float v;
                v = s0 + tg.x; v = fmaxf(v, 0.2f * v); const float e00 = __expf(ma.x + v);
                v = s0 + tg.y; v = fmaxf(v, 0.2f * v); const float e01 = __expf(ma.y + v);
                v = s1 + tg.x; v = fmaxf(v, 0.2f * v); const float e10 = __expf(mb.x + v);
                v = s1 + tg.y; v = fmaxf(v, 0.2f * v); const float e11 = __expf(mb.y + v);
                __nv_bfloat162 p0 = __floats2bfloat162_rn(e00, e01);
                __nv_bfloat162 p1 = __floats2bfloat162_rn(e10, e11);
                areg[kc][hf * 2 + 0] = *(uint32_t*)&p0;
                areg[kc][hf * 2 + 1] = *(uint32_t*)&p1;
            }
        }

        // ---- issue next-stage global loads (overlap with HMMA) ----
        if (kt < 63) {
            const int j1 = j0 + 64;
#pragma unroll
            for (int kc = 0; kc < 4; kc++)
#pragma unroll
                for (int hf = 0; hf < 2; hf++) {
                    const int c = j1 + kc * 16 + hf * 8 + q2;
                    mvA[kc * 2 + hf] = *(const float2*)(g_mask + (size_t)(i0 + row0l) * NTOT + c);
                    mvB[kc * 2 + hf] = *(const float2*)(g_mask + (size_t)(i0 + row1l) * NTOT + c);
                }
            const __nv_bfloat16* src = g_Bt + ((size_t)h * FOUT + bf) * NTOT + j1 + bq * 16;
            bv0 = *(const uint4*)(src);
            bv1 = *(const uint4*)(src + 8);
        }

        // ---- HMMA on stage kt ----
        const uint32_t bb = smbB + b * 8192;
#pragma unroll
        for (int kc = 0; kc < 4; kc++) {
#pragma unroll
            for (int nt = 0; nt < 4; nt++) {
                uint32_t br_[4];
                ldm4(br_, bb + offB[nt][kc]);
                mma16816(acc[nt * 2 + 0], areg[kc], br_[0], br_[2]);
                mma16816(acc[nt * 2 + 1], areg[kc], br_[1], br_[3]);
            }
        }
        __syncthreads();
    }

    // ---- epilogue: + skip, ELU, store ----
#pragma unroll
    for (int nt = 0; nt < 8; nt++) {
        const int col = h * 64 + nt * 8 + q2;
        {
            const int row = i0 + row0l;
            const float2 sk = *(const float2*)(g_S + (size_t)row * NCOL + col);
            float vx = acc[nt][0] + sk.x;
            float vy = acc[nt][1] + sk.y;
            float2 o;
            o.x = vx > 0.f ? vx : expm1f(vx);
            o.y = vy > 0.f ? vy : expm1f(vy);
            *(float2*)(outY + (size_t)row * NCOL + col) = o;
        }
        {
            const int row = i0 + row1l;
            const float2 sk = *(const float2*)(g_S + (size_t)row * NCOL + col);
            float vx = acc[nt][2] + sk.x;
            float vy = acc[nt][3] + sk.y;
            float2 o;
            o.x = vx > 0.f ? vx : expm1f(vx);
            o.y = vy > 0.f ? vy : expm1f(vy);
            *(float2*)(outY + (size_t)row * NCOL + col) = o;
        }
    }
}

// ---------------- launch ----------------
extern "C" void kernel_launch(void* const* d_in, const int* in_sizes, int n_in,
                              void* d_out, int out_size) {
    const float* x    = (const float*)d_in[0];
    const float* deg  = (const float*)d_in[1];
    const float* bond = (const float*)d_in[3];
    const float* wp   = (const float*)d_in[4];
    const float* wsrc = (const float*)d_in[5];
    const float* wtgt = (const float*)d_in[6];
    const float* wsk  = (const float*)d_in[7];
    const int*   cutp = (const int*)d_in[8];

    float* outY  = (float*)d_out;
    float* outLN = (float*)d_out + NTOT * NCOL;

    k_gemm1<<<dim3(32, 8), 256>>>(x, wp, wsk);
    k_scores<<<64, 256>>>(wsrc, wtgt);
    k_mask<<<dim3(32, 32), 256>>>(deg, bond, cutp);
    k_finalize<<<256, 256>>>();
    k_attn<<<dim3(32, 4), 256>>>(outY, outLN);
}